// round 14
// baseline (speedup 1.0000x reference)
#include <cuda_runtime.h>

#define NVERT 8192
#define GRES 64
#define NVOX (GRES*GRES*GRES)   // 262144
#define NMAX 1048576
#define SCANB 512               // 512 blocks x 512 threads covers NVOX
#define FULLM 0xFFFFFFFFu

// ---------------- scratch (device globals; no allocation) ----------------
__device__ unsigned int g_mm[6];        // sortable-uint min(x,y,z), max(x,y,z)
__device__ int g_hist[NVOX];
__device__ int g_off[NVOX + 1];
__device__ int g_cur[NVOX];
__device__ int g_bsum[SCANB];
__device__ int g_bbase[SCANB];
__device__ int g_vid[NMAX];
__device__ float4 g_pts[NMAX];          // voxel-sorted points {x,y,z,bits(origidx)}
__device__ float4 g_vert[NVERT];        // raw {x, y, z, |v|^2}
// vertex grid for pruned knn
__device__ int v_hist[NVOX];
__device__ int v_off[NVOX + 1];
__device__ int v_cur[NVOX];
__device__ int v_cell[NVERT];
__device__ float4 g_vs[NVERT];          // cell-sorted, prescaled {2x,2y,2z,|v|^2}
__device__ unsigned short g_vsidx[NVERT];

// monotone float<->uint mapping (min/max via integer atomics)
__device__ __forceinline__ unsigned f2o(float f) {
    unsigned b = __float_as_uint(f);
    return (b & 0x80000000u) ? ~b : (b | 0x80000000u);
}
__device__ __forceinline__ float o2f(unsigned o) {
    unsigned b = (o & 0x80000000u) ? (o & 0x7FFFFFFFu) : ~o;
    return __uint_as_float(b);
}

// shared helper: per-axis extent guards (must match k_vidhist exactly)
__device__ __forceinline__ void grid_params(float& mnx, float& mny, float& mnz,
                                            float& dx, float& dy, float& dz) {
    mnx = o2f(g_mm[0]); mny = o2f(g_mm[1]); mnz = o2f(g_mm[2]);
    float exx = __fsub_rn(o2f(g_mm[3]), mnx);
    float exy = __fsub_rn(o2f(g_mm[4]), mny);
    float exz = __fsub_rn(o2f(g_mm[5]), mnz);
    dx = exx > 0.f ? exx : 1.f;
    dy = exy > 0.f ? exy : 1.f;
    dz = exz > 0.f ? exz : 1.f;
}

// ---------------- 2. global min/max per coordinate ----------------
__global__ void k_minmax(const float* __restrict__ xyz, int n) {
    float mnx = 3.402823466e38f, mny = mnx, mnz = mnx;
    float mxx = -3.402823466e38f, mxy = mxx, mxz = mxx;
    for (int i = blockIdx.x * blockDim.x + threadIdx.x; i < n;
         i += gridDim.x * blockDim.x) {
        float x = xyz[3 * i], y = xyz[3 * i + 1], z = xyz[3 * i + 2];
        mnx = fminf(mnx, x); mny = fminf(mny, y); mnz = fminf(mnz, z);
        mxx = fmaxf(mxx, x); mxy = fmaxf(mxy, y); mxz = fmaxf(mxz, z);
    }
    for (int o = 16; o; o >>= 1) {
        mnx = fminf(mnx, __shfl_xor_sync(FULLM, mnx, o));
        mny = fminf(mny, __shfl_xor_sync(FULLM, mny, o));
        mnz = fminf(mnz, __shfl_xor_sync(FULLM, mnz, o));
        mxx = fmaxf(mxx, __shfl_xor_sync(FULLM, mxx, o));
        mxy = fmaxf(mxy, __shfl_xor_sync(FULLM, mxy, o));
        mxz = fmaxf(mxz, __shfl_xor_sync(FULLM, mxz, o));
    }
    if ((threadIdx.x & 31) == 0) {
        atomicMin(&g_mm[0], f2o(mnx));
        atomicMin(&g_mm[1], f2o(mny));
        atomicMin(&g_mm[2], f2o(mnz));
        atomicMax(&g_mm[3], f2o(mxx));
        atomicMax(&g_mm[4], f2o(mxy));
        atomicMax(&g_mm[5], f2o(mxz));
    }
}

// ---------------- 3. voxel id + histogram (reciprocal-hoisted division) ----
__global__ void k_vidhist(const float* __restrict__ xyz, int n) {
    float mnx, mny, mnz, dx, dy, dz;
    grid_params(mnx, mny, mnz, dx, dy, dz);
    float rx = __fdiv_rn(1.0f, dx);
    float ry = __fdiv_rn(1.0f, dy);
    float rz = __fdiv_rn(1.0f, dz);
    const float HI = (float)(1.0 - 1e-6);
    for (int i = blockIdx.x * blockDim.x + threadIdx.x; i < n;
         i += gridDim.x * blockDim.x) {
        float ux = __fmul_rn(__fsub_rn(xyz[3 * i],     mnx), rx);
        float uy = __fmul_rn(__fsub_rn(xyz[3 * i + 1], mny), ry);
        float uz = __fmul_rn(__fsub_rn(xyz[3 * i + 2], mnz), rz);
        ux = fminf(fmaxf(ux, 0.f), HI);
        uy = fminf(fmaxf(uy, 0.f), HI);
        uz = fminf(fmaxf(uz, 0.f), HI);
        int vx = (int)floorf(__fmul_rn(ux, (float)GRES));
        int vy = (int)floorf(__fmul_rn(uy, (float)GRES));
        int vz = (int)floorf(__fmul_rn(uz, (float)GRES));
        int vid = (vx * GRES + vy) * GRES + vz;
        g_vid[i] = vid;
        atomicAdd(&g_hist[vid], 1);
    }
}

// ---------------- 4. generic exclusive scan over NVOX (3 kernels) ----------
__global__ void k_scan_a(const int* __restrict__ hist) {
    __shared__ int sh[512];
    int i = blockIdx.x * 512 + threadIdx.x;
    sh[threadIdx.x] = hist[i];
    __syncthreads();
    for (int off = 256; off; off >>= 1) {
        if (threadIdx.x < off) sh[threadIdx.x] += sh[threadIdx.x + off];
        __syncthreads();
    }
    if (threadIdx.x == 0) g_bsum[blockIdx.x] = sh[0];
}
__global__ void k_scan_b(int* __restrict__ off, int total) {
    __shared__ int sh[512];
    int v = g_bsum[threadIdx.x];
    sh[threadIdx.x] = v;
    __syncthreads();
    for (int o = 1; o < 512; o <<= 1) {
        int t = (threadIdx.x >= o) ? sh[threadIdx.x - o] : 0;
        __syncthreads();
        sh[threadIdx.x] += t;
        __syncthreads();
    }
    g_bbase[threadIdx.x] = sh[threadIdx.x] - v;
    if (threadIdx.x == 0) off[NVOX] = total;
}
__global__ void k_scan_c(const int* __restrict__ hist, int* __restrict__ off,
                         int* __restrict__ cur) {
    __shared__ int sh[512];
    int i = blockIdx.x * 512 + threadIdx.x;
    int v = hist[i];
    sh[threadIdx.x] = v;
    __syncthreads();
    for (int o = 1; o < 512; o <<= 1) {
        int t = (threadIdx.x >= o) ? sh[threadIdx.x - o] : 0;
        __syncthreads();
        sh[threadIdx.x] += t;
        __syncthreads();
    }
    int excl = sh[threadIdx.x] - v + g_bbase[blockIdx.x];
    off[i] = excl;
    cur[i] = excl;
}

// ---------------- 5. counting-sort scatter: packed point records -----------
__global__ void k_scatter(const float* __restrict__ xyz, int n) {
    for (int i = blockIdx.x * blockDim.x + threadIdx.x; i < n;
         i += gridDim.x * blockDim.x) {
        int v = g_vid[i];
        int pos = atomicAdd(&g_cur[v], 1);
        g_pts[pos] = make_float4(xyz[3 * i], xyz[3 * i + 1], xyz[3 * i + 2],
                                 __int_as_float(i));
    }
}

// ---------------- 6. stable selection of 8192 vertices (+ vertex binning) --
// sel per f32 jnp.linspace: delta = RN((n-1)/8191); s = floor(RN(q*delta)).
__global__ void k_select(float* __restrict__ out, int n) {
    __shared__ int sb[4096];
    __shared__ int info[3];
    int q = blockIdx.x;
    if (threadIdx.x == 0) {
        float delta = __fdiv_rn((float)(n - 1), (float)(NVERT - 1));
        float fv = __fmul_rn((float)q, delta);
        int s = (int)floorf(fv);
        int lo = 0, hi = NVOX;
        while (hi - lo > 1) {
            int mid = (lo + hi) >> 1;
            if (g_off[mid] <= s) lo = mid; else hi = mid;
        }
        info[0] = g_off[lo];
        info[1] = g_off[lo + 1] - g_off[lo];
        info[2] = s - g_off[lo];
    }
    __syncthreads();
    int base = info[0], m = info[1], r = info[2];

    float mnx, mny, mnz, dx, dy, dz;
    grid_params(mnx, mny, mnz, dx, dy, dz);
    float ivx = __fdiv_rn((float)GRES, dx);
    float ivy = __fdiv_rn((float)GRES, dy);
    float ivz = __fdiv_rn((float)GRES, dz);

    if (m <= 4096) {
        for (int j = threadIdx.x; j < m; j += blockDim.x)
            sb[j] = __float_as_int(g_pts[base + j].w);
        __syncthreads();
        for (int j = threadIdx.x; j < m; j += blockDim.x) {
            int x = sb[j], c = 0;
            for (int t = 0; t < m; t++) c += (sb[t] < x);
            if (c == r) {
                float4 P = g_pts[base + j];
                out[3 * q] = P.x; out[3 * q + 1] = P.y; out[3 * q + 2] = P.z;
                float vn = __fadd_rn(__fadd_rn(__fmul_rn(P.x, P.x), __fmul_rn(P.y, P.y)),
                                     __fmul_rn(P.z, P.z));
                g_vert[q] = make_float4(P.x, P.y, P.z, vn);
                int cx = min(max((int)floorf((P.x - mnx) * ivx), 0), GRES - 1);
                int cy = min(max((int)floorf((P.y - mny) * ivy), 0), GRES - 1);
                int cz = min(max((int)floorf((P.z - mnz) * ivz), 0), GRES - 1);
                int cell = (cx * GRES + cy) * GRES + cz;
                v_cell[q] = cell;
                atomicAdd(&v_hist[cell], 1);
            }
        }
    } else {
        for (int j = threadIdx.x; j < m; j += blockDim.x) {
            int x = __float_as_int(g_pts[base + j].w), c = 0;
            for (int t = 0; t < m; t++)
                c += (__float_as_int(g_pts[base + t].w) < x);
            if (c == r) {
                float4 P = g_pts[base + j];
                out[3 * q] = P.x; out[3 * q + 1] = P.y; out[3 * q + 2] = P.z;
                float vn = __fadd_rn(__fadd_rn(__fmul_rn(P.x, P.x), __fmul_rn(P.y, P.y)),
                                     __fmul_rn(P.z, P.z));
                g_vert[q] = make_float4(P.x, P.y, P.z, vn);
                int cx = min(max((int)floorf((P.x - mnx) * ivx), 0), GRES - 1);
                int cy = min(max((int)floorf((P.y - mny) * ivy), 0), GRES - 1);
                int cz = min(max((int)floorf((P.z - mnz) * ivz), 0), GRES - 1);
                int cell = (cx * GRES + cy) * GRES + cz;
                v_cell[q] = cell;
                atomicAdd(&v_hist[cell], 1);
            }
        }
    }
}

// ---------------- 6c. scatter vertices (prescaled by 2) --------------------
__global__ void k_vscatter() {
    int q = blockIdx.x * blockDim.x + threadIdx.x;
    if (q >= NVERT) return;
    int c = v_cell[q];
    int pos = atomicAdd(&v_cur[c], 1);
    float4 v = g_vert[q];
    g_vs[pos] = make_float4(2.0f * v.x, 2.0f * v.y, 2.0f * v.z, v.w);
    g_vsidx[pos] = (unsigned short)q;
}

// ---------------- 7. grid-pruned 1-NN + warp-cooperative outlier path ------
// Bulk points: octant phase A (MLP=8) + exact phase B (unchanged, champion).
// Outliers (empty octant OR phase-B box > 16 rows — Gaussian tail): the
// whole warp brute-forces all 8192 shared vertices cooperatively with the
// exact formula (256 evals/lane, LDS-throughput bound) + lexicographic
// (d, orig_idx) shuffle reduce. Exact by construction; kills the serialized
// expanding-box crawl that dominated runtime.
__global__ void __launch_bounds__(1024, 1)
k_knn(float* __restrict__ out, int n) {
    extern __shared__ char smem[];
    float4* sv = (float4*)smem;                         // 8192 * 16B
    unsigned short* sidx = (unsigned short*)(smem + NVERT * sizeof(float4));
    for (int j = threadIdx.x; j < NVERT; j += blockDim.x) {
        sv[j] = g_vs[j];
        sidx[j] = g_vsidx[j];
    }
    __syncthreads();

    float mnx, mny, mnz, dx, dy, dz;
    grid_params(mnx, mny, mnz, dx, dy, dz);
    float ivx = __fdiv_rn((float)GRES, dx);
    float ivy = __fdiv_rn((float)GRES, dy);
    float ivz = __fdiv_rn((float)GRES, dz);
    float* pout = out + 3 * NVERT;
    int lane = threadIdx.x & 31;

    for (int i = blockIdx.x * blockDim.x + threadIdx.x; i < n;
         i += gridDim.x * blockDim.x) {
        float4 P = g_pts[i];                // coalesced
        float px = P.x, py = P.y, pz = P.z;
        int p = __float_as_int(P.w);
        float fx = (px - mnx) * ivx, fy = (py - mny) * ivy, fz = (pz - mnz) * ivz;
        int cx = min(max((int)floorf(fx), 0), GRES - 1);
        int cy = min(max((int)floorf(fy), 0), GRES - 1);
        int cz = min(max((int)floorf(fz), 0), GRES - 1);

        // ---- phase A: octant 2^3 box, bounds prefetched with MLP=8 ----
        float bestD = 3.402823466e38f;
        {
            int x0 = (fx - (float)cx > 0.5f) ? cx : cx - 1;
            int y0 = (fy - (float)cy > 0.5f) ? cy : cy - 1;
            int z0 = (fz - (float)cz > 0.5f) ? cz : cz - 1;
            x0 = max(x0, 0); int x1 = min(x0 + 1, GRES - 1); x0 = min(x0, x1);
            y0 = max(y0, 0); int y1 = min(y0 + 1, GRES - 1); y0 = min(y0, y1);
            z0 = max(z0, 0); int z1 = min(z0 + 1, GRES - 1); z0 = min(z0, z1);
            int r00 = (x0 * GRES + y0) * GRES;
            int r01 = (x0 * GRES + y1) * GRES;
            int r10 = (x1 * GRES + y0) * GRES;
            int r11 = (x1 * GRES + y1) * GRES;
            int s00 = v_off[r00 + z0], e00 = v_off[r00 + z1 + 1];
            int s01 = v_off[r01 + z0], e01 = v_off[r01 + z1 + 1];
            int s10 = v_off[r10 + z0], e10 = v_off[r10 + z1 + 1];
            int s11 = v_off[r11 + z0], e11 = v_off[r11 + z1 + 1];
            #pragma unroll 1
            for (int j = s00; j < e00; j++) {
                float4 V = sv[j];
                float ddx = px - 0.5f * V.x, ddy = py - 0.5f * V.y, ddz = pz - 0.5f * V.z;
                bestD = fminf(bestD, fmaf(ddz, ddz, fmaf(ddy, ddy, ddx * ddx)));
            }
            #pragma unroll 1
            for (int j = s01; j < e01; j++) {
                float4 V = sv[j];
                float ddx = px - 0.5f * V.x, ddy = py - 0.5f * V.y, ddz = pz - 0.5f * V.z;
                bestD = fminf(bestD, fmaf(ddz, ddz, fmaf(ddy, ddy, ddx * ddx)));
            }
            #pragma unroll 1
            for (int j = s10; j < e10; j++) {
                float4 V = sv[j];
                float ddx = px - 0.5f * V.x, ddy = py - 0.5f * V.y, ddz = pz - 0.5f * V.z;
                bestD = fminf(bestD, fmaf(ddz, ddz, fmaf(ddy, ddy, ddx * ddx)));
            }
            #pragma unroll 1
            for (int j = s11; j < e11; j++) {
                float4 V = sv[j];
                float ddx = px - 0.5f * V.x, ddy = py - 0.5f * V.y, ddz = pz - 0.5f * V.z;
                bestD = fminf(bestD, fmaf(ddz, ddz, fmaf(ddy, ddy, ddx * ddx)));
            }
        }

        // ---- classify + phase B box ----
        bool brute = (bestD >= 3.0e38f);
        float R = brute ? 0.0f : (sqrtf(bestD + 1e-4f) + 1e-4f);
        int x0 = min(max((int)floorf((px - R - mnx) * ivx), 0), GRES - 1);
        int x1 = min(max((int)floorf((px + R - mnx) * ivx), 0), GRES - 1);
        int y0 = min(max((int)floorf((py - R - mny) * ivy), 0), GRES - 1);
        int y1 = min(max((int)floorf((py + R - mny) * ivy), 0), GRES - 1);
        int z0 = min(max((int)floorf((pz - R - mnz) * ivz), 0), GRES - 1);
        int z1 = min(max((int)floorf((pz + R - mnz) * ivz), 0), GRES - 1);
        int nr = (x1 - x0 + 1) * (y1 - y0 + 1);
        brute = brute || (nr > 16) || ((z1 - z0 + 1) > 5);
        unsigned bm = __ballot_sync(FULLM, brute);

        float bd = 3.402823466e38f;
        int bi = 0x7FFFFFFF;

        if (!brute) {
            // ---- phase B: exact rescan, 1-ahead row prefetch (champion) ----
            int ix = x0, iy = y0;
            int rowb = (ix * GRES + iy) * GRES;
            int sC = v_off[rowb + z0], eC = v_off[rowb + z1 + 1];
            for (int r = 0; r < nr; r++) {
                int nix = ix, niy = iy + 1;
                if (niy > y1) { niy = y0; nix = ix + 1; }
                int sN = 0, eN = 0;
                if (r + 1 < nr) {
                    int nb = (nix * GRES + niy) * GRES;
                    sN = v_off[nb + z0];
                    eN = v_off[nb + z1 + 1];
                }
                #pragma unroll 1
                for (int j = sC; j < eC; j++) {
                    float4 V = sv[j];
                    float t2 = fmaf(pz, V.z, fmaf(py, V.y, __fmul_rn(px, V.x)));
                    float d = __fsub_rn(V.w, t2);
                    int oi = sidx[j];
                    if (d < bd || (d == bd && oi < bi)) { bd = d; bi = oi; }
                }
                sC = sN; eC = eN; ix = nix; iy = niy;
            }
        }

        // ---- cooperative brute force for flagged lanes ----
        while (bm) {
            int src = __ffs(bm) - 1;
            bm &= bm - 1;
            float qx = __shfl_sync(FULLM, px, src);
            float qy = __shfl_sync(FULLM, py, src);
            float qz = __shfl_sync(FULLM, pz, src);
            float bbd = 3.402823466e38f;
            int bbi = 0x7FFFFFFF;
            #pragma unroll 4
            for (int j = lane; j < NVERT; j += 32) {
                float4 V = sv[j];
                float t2 = fmaf(qz, V.z, fmaf(qy, V.y, __fmul_rn(qx, V.x)));
                float d = __fsub_rn(V.w, t2);
                int oi = sidx[j];
                if (d < bbd || (d == bbd && oi < bbi)) { bbd = d; bbi = oi; }
            }
            for (int o = 16; o; o >>= 1) {
                float od = __shfl_xor_sync(FULLM, bbd, o);
                int oi2 = __shfl_xor_sync(FULLM, bbi, o);
                if (od < bbd || (od == bbd && oi2 < bbi)) { bbd = od; bbi = oi2; }
            }
            if (lane == src) { bd = bbd; bi = bbi; }
        }
        pout[p] = (float)bi;
    }
}

// ---------------- launch ----------------
extern "C" void kernel_launch(void* const* d_in, const int* in_sizes, int n_in,
                              void* d_out, int out_size) {
    const float* xyz = (const float*)d_in[0];
    int n = in_sizes[0] / 3;
    float* out = (float*)d_out;

    int* d_ghist; cudaGetSymbolAddress((void**)&d_ghist, g_hist);
    int* d_goff;  cudaGetSymbolAddress((void**)&d_goff,  g_off);
    int* d_gcur;  cudaGetSymbolAddress((void**)&d_gcur,  g_cur);
    int* d_vhist; cudaGetSymbolAddress((void**)&d_vhist, v_hist);
    int* d_voff;  cudaGetSymbolAddress((void**)&d_voff,  v_off);
    int* d_vcur;  cudaGetSymbolAddress((void**)&d_vcur,  v_cur);
    unsigned int* d_mm; cudaGetSymbolAddress((void**)&d_mm, g_mm);

    // init via memset nodes
    cudaMemsetAsync(d_ghist, 0, NVOX * sizeof(int));
    cudaMemsetAsync(d_vhist, 0, NVOX * sizeof(int));
    cudaMemsetAsync(d_mm, 0xFF, 3 * sizeof(unsigned int));
    cudaMemsetAsync(d_mm + 3, 0x00, 3 * sizeof(unsigned int));

    k_minmax<<<148, 256>>>(xyz, n);
    k_vidhist<<<1024, 256>>>(xyz, n);
    k_scan_a<<<SCANB, 512>>>(d_ghist);
    k_scan_b<<<1, 512>>>(d_goff, n);
    k_scan_c<<<SCANB, 512>>>(d_ghist, d_goff, d_gcur);
    k_scatter<<<1024, 256>>>(xyz, n);
    k_select<<<NVERT, 128>>>(out, n);
    k_scan_a<<<SCANB, 512>>>(d_vhist);
    k_scan_b<<<1, 512>>>(d_voff, NVERT);
    k_scan_c<<<SCANB, 512>>>(d_vhist, d_voff, d_vcur);
    k_vscatter<<<16, 512>>>();

    int smem = NVERT * (int)sizeof(float4) + NVERT * (int)sizeof(unsigned short);
    cudaFuncSetAttribute(k_knn, cudaFuncAttributeMaxDynamicSharedMemorySize, smem);
    k_knn<<<148, 1024, smem>>>(out, n);
}

// round 15
// speedup vs baseline: 1.0164x; 1.0164x over previous
#include <cuda_runtime.h>

#define NVERT 8192
#define GRES 64
#define NVOX (GRES*GRES*GRES)   // 262144
#define NMAX 1048576
#define SCANB 512               // 512 blocks x 512 threads covers NVOX
#define FULLM 0xFFFFFFFFu

// ---------------- scratch (device globals; no allocation) ----------------
__device__ unsigned int g_mm[6];        // sortable-uint min(x,y,z), max(x,y,z)
__device__ int g_hist[NVOX];
__device__ int g_off[NVOX + 1];
__device__ int g_cur[NVOX];
__device__ int g_bsum[SCANB];
__device__ int g_bbase[SCANB];
__device__ int g_vid[NMAX];
__device__ float4 g_pts[NMAX];          // voxel-sorted points {x,y,z,bits(origidx)}
__device__ float4 g_vert[NVERT];        // raw {x, y, z, |v|^2}
// vertex grid for pruned knn
__device__ int v_hist[NVOX];
__device__ int v_off[NVOX + 1];
__device__ int v_cur[NVOX];
__device__ int v_cell[NVERT];
__device__ float4 g_vs[NVERT];          // cell-sorted, prescaled {2x,2y,2z,|v|^2}
__device__ unsigned short g_vsidx[NVERT];

// monotone float<->uint mapping (min/max via integer atomics)
__device__ __forceinline__ unsigned f2o(float f) {
    unsigned b = __float_as_uint(f);
    return (b & 0x80000000u) ? ~b : (b | 0x80000000u);
}
__device__ __forceinline__ float o2f(unsigned o) {
    unsigned b = (o & 0x80000000u) ? (o & 0x7FFFFFFFu) : ~o;
    return __uint_as_float(b);
}

// shared helper: per-axis extent guards (must match k_vidhist exactly)
__device__ __forceinline__ void grid_params(float& mnx, float& mny, float& mnz,
                                            float& dx, float& dy, float& dz) {
    mnx = o2f(g_mm[0]); mny = o2f(g_mm[1]); mnz = o2f(g_mm[2]);
    float exx = __fsub_rn(o2f(g_mm[3]), mnx);
    float exy = __fsub_rn(o2f(g_mm[4]), mny);
    float exz = __fsub_rn(o2f(g_mm[5]), mnz);
    dx = exx > 0.f ? exx : 1.f;
    dy = exy > 0.f ? exy : 1.f;
    dz = exz > 0.f ? exz : 1.f;
}

// ---------------- 2. global min/max per coordinate ----------------
__global__ void k_minmax(const float* __restrict__ xyz, int n) {
    float mnx = 3.402823466e38f, mny = mnx, mnz = mnx;
    float mxx = -3.402823466e38f, mxy = mxx, mxz = mxx;
    for (int i = blockIdx.x * blockDim.x + threadIdx.x; i < n;
         i += gridDim.x * blockDim.x) {
        float x = xyz[3 * i], y = xyz[3 * i + 1], z = xyz[3 * i + 2];
        mnx = fminf(mnx, x); mny = fminf(mny, y); mnz = fminf(mnz, z);
        mxx = fmaxf(mxx, x); mxy = fmaxf(mxy, y); mxz = fmaxf(mxz, z);
    }
    for (int o = 16; o; o >>= 1) {
        mnx = fminf(mnx, __shfl_xor_sync(FULLM, mnx, o));
        mny = fminf(mny, __shfl_xor_sync(FULLM, mny, o));
        mnz = fminf(mnz, __shfl_xor_sync(FULLM, mnz, o));
        mxx = fmaxf(mxx, __shfl_xor_sync(FULLM, mxx, o));
        mxy = fmaxf(mxy, __shfl_xor_sync(FULLM, mxy, o));
        mxz = fmaxf(mxz, __shfl_xor_sync(FULLM, mxz, o));
    }
    if ((threadIdx.x & 31) == 0) {
        atomicMin(&g_mm[0], f2o(mnx));
        atomicMin(&g_mm[1], f2o(mny));
        atomicMin(&g_mm[2], f2o(mnz));
        atomicMax(&g_mm[3], f2o(mxx));
        atomicMax(&g_mm[4], f2o(mxy));
        atomicMax(&g_mm[5], f2o(mxz));
    }
}

// ---------------- 3. voxel id + histogram (reciprocal-hoisted division) ----
__global__ void k_vidhist(const float* __restrict__ xyz, int n) {
    float mnx, mny, mnz, dx, dy, dz;
    grid_params(mnx, mny, mnz, dx, dy, dz);
    float rx = __fdiv_rn(1.0f, dx);
    float ry = __fdiv_rn(1.0f, dy);
    float rz = __fdiv_rn(1.0f, dz);
    const float HI = (float)(1.0 - 1e-6);
    for (int i = blockIdx.x * blockDim.x + threadIdx.x; i < n;
         i += gridDim.x * blockDim.x) {
        float ux = __fmul_rn(__fsub_rn(xyz[3 * i],     mnx), rx);
        float uy = __fmul_rn(__fsub_rn(xyz[3 * i + 1], mny), ry);
        float uz = __fmul_rn(__fsub_rn(xyz[3 * i + 2], mnz), rz);
        ux = fminf(fmaxf(ux, 0.f), HI);
        uy = fminf(fmaxf(uy, 0.f), HI);
        uz = fminf(fmaxf(uz, 0.f), HI);
        int vx = (int)floorf(__fmul_rn(ux, (float)GRES));
        int vy = (int)floorf(__fmul_rn(uy, (float)GRES));
        int vz = (int)floorf(__fmul_rn(uz, (float)GRES));
        int vid = (vx * GRES + vy) * GRES + vz;
        g_vid[i] = vid;
        atomicAdd(&g_hist[vid], 1);
    }
}

// ---------------- 4. generic exclusive scan over NVOX (3 kernels) ----------
__global__ void k_scan_a(const int* __restrict__ hist) {
    __shared__ int sh[512];
    int i = blockIdx.x * 512 + threadIdx.x;
    sh[threadIdx.x] = hist[i];
    __syncthreads();
    for (int off = 256; off; off >>= 1) {
        if (threadIdx.x < off) sh[threadIdx.x] += sh[threadIdx.x + off];
        __syncthreads();
    }
    if (threadIdx.x == 0) g_bsum[blockIdx.x] = sh[0];
}
__global__ void k_scan_b(int* __restrict__ off, int total) {
    __shared__ int sh[512];
    int v = g_bsum[threadIdx.x];
    sh[threadIdx.x] = v;
    __syncthreads();
    for (int o = 1; o < 512; o <<= 1) {
        int t = (threadIdx.x >= o) ? sh[threadIdx.x - o] : 0;
        __syncthreads();
        sh[threadIdx.x] += t;
        __syncthreads();
    }
    g_bbase[threadIdx.x] = sh[threadIdx.x] - v;
    if (threadIdx.x == 0) off[NVOX] = total;
}
__global__ void k_scan_c(const int* __restrict__ hist, int* __restrict__ off,
                         int* __restrict__ cur) {
    __shared__ int sh[512];
    int i = blockIdx.x * 512 + threadIdx.x;
    int v = hist[i];
    sh[threadIdx.x] = v;
    __syncthreads();
    for (int o = 1; o < 512; o <<= 1) {
        int t = (threadIdx.x >= o) ? sh[threadIdx.x - o] : 0;
        __syncthreads();
        sh[threadIdx.x] += t;
        __syncthreads();
    }
    int excl = sh[threadIdx.x] - v + g_bbase[blockIdx.x];
    off[i] = excl;
    cur[i] = excl;
}

// ---------------- 5. counting-sort scatter: packed point records -----------
__global__ void k_scatter(const float* __restrict__ xyz, int n) {
    for (int i = blockIdx.x * blockDim.x + threadIdx.x; i < n;
         i += gridDim.x * blockDim.x) {
        int v = g_vid[i];
        int pos = atomicAdd(&g_cur[v], 1);
        g_pts[pos] = make_float4(xyz[3 * i], xyz[3 * i + 1], xyz[3 * i + 2],
                                 __int_as_float(i));
    }
}

// ---------------- 6. stable selection of 8192 vertices (+ vertex binning) --
// sel per f32 jnp.linspace: delta = RN((n-1)/8191); s = floor(RN(q*delta)).
__global__ void k_select(float* __restrict__ out, int n) {
    __shared__ int sb[4096];
    __shared__ int info[3];
    int q = blockIdx.x;
    if (threadIdx.x == 0) {
        float delta = __fdiv_rn((float)(n - 1), (float)(NVERT - 1));
        float fv = __fmul_rn((float)q, delta);
        int s = (int)floorf(fv);
        int lo = 0, hi = NVOX;
        while (hi - lo > 1) {
            int mid = (lo + hi) >> 1;
            if (g_off[mid] <= s) lo = mid; else hi = mid;
        }
        info[0] = g_off[lo];
        info[1] = g_off[lo + 1] - g_off[lo];
        info[2] = s - g_off[lo];
    }
    __syncthreads();
    int base = info[0], m = info[1], r = info[2];

    float mnx, mny, mnz, dx, dy, dz;
    grid_params(mnx, mny, mnz, dx, dy, dz);
    float ivx = __fdiv_rn((float)GRES, dx);
    float ivy = __fdiv_rn((float)GRES, dy);
    float ivz = __fdiv_rn((float)GRES, dz);

    if (m <= 4096) {
        for (int j = threadIdx.x; j < m; j += blockDim.x)
            sb[j] = __float_as_int(g_pts[base + j].w);
        __syncthreads();
        for (int j = threadIdx.x; j < m; j += blockDim.x) {
            int x = sb[j], c = 0;
            for (int t = 0; t < m; t++) c += (sb[t] < x);
            if (c == r) {
                float4 P = g_pts[base + j];
                out[3 * q] = P.x; out[3 * q + 1] = P.y; out[3 * q + 2] = P.z;
                float vn = __fadd_rn(__fadd_rn(__fmul_rn(P.x, P.x), __fmul_rn(P.y, P.y)),
                                     __fmul_rn(P.z, P.z));
                g_vert[q] = make_float4(P.x, P.y, P.z, vn);
                int cx = min(max((int)floorf((P.x - mnx) * ivx), 0), GRES - 1);
                int cy = min(max((int)floorf((P.y - mny) * ivy), 0), GRES - 1);
                int cz = min(max((int)floorf((P.z - mnz) * ivz), 0), GRES - 1);
                int cell = (cx * GRES + cy) * GRES + cz;
                v_cell[q] = cell;
                atomicAdd(&v_hist[cell], 1);
            }
        }
    } else {
        for (int j = threadIdx.x; j < m; j += blockDim.x) {
            int x = __float_as_int(g_pts[base + j].w), c = 0;
            for (int t = 0; t < m; t++)
                c += (__float_as_int(g_pts[base + t].w) < x);
            if (c == r) {
                float4 P = g_pts[base + j];
                out[3 * q] = P.x; out[3 * q + 1] = P.y; out[3 * q + 2] = P.z;
                float vn = __fadd_rn(__fadd_rn(__fmul_rn(P.x, P.x), __fmul_rn(P.y, P.y)),
                                     __fmul_rn(P.z, P.z));
                g_vert[q] = make_float4(P.x, P.y, P.z, vn);
                int cx = min(max((int)floorf((P.x - mnx) * ivx), 0), GRES - 1);
                int cy = min(max((int)floorf((P.y - mny) * ivy), 0), GRES - 1);
                int cz = min(max((int)floorf((P.z - mnz) * ivz), 0), GRES - 1);
                int cell = (cx * GRES + cy) * GRES + cz;
                v_cell[q] = cell;
                atomicAdd(&v_hist[cell], 1);
            }
        }
    }
}

// ---------------- 6c. scatter vertices (prescaled by 2) --------------------
__global__ void k_vscatter() {
    int q = blockIdx.x * blockDim.x + threadIdx.x;
    if (q >= NVERT) return;
    int c = v_cell[q];
    int pos = atomicAdd(&v_cur[c], 1);
    float4 v = g_vert[q];
    g_vs[pos] = make_float4(2.0f * v.x, 2.0f * v.y, 2.0f * v.z, v.w);
    g_vsidx[pos] = (unsigned short)q;
}

// ---------------- 7. grid-pruned 1-NN; brute ONLY for empty octant ---------
// Bulk path byte-identical to the 493us champion (octant phase A with MLP=8
// prefetch, exact phase B over tight sphere box with 1-ahead row prefetch).
// ONLY change: points whose octant is empty (deep Gaussian tail, ~1e-3 of
// points) take a warp-cooperative exact brute-force over all 8192 vertices
// (bounded ~2-4K cyc) instead of the serialized O(w^3) expanding-box crawl.
// Strictly dominates: no point is more expensive than in the champion.
__global__ void __launch_bounds__(1024, 1)
k_knn(float* __restrict__ out, int n) {
    extern __shared__ char smem[];
    float4* sv = (float4*)smem;                         // 8192 * 16B
    unsigned short* sidx = (unsigned short*)(smem + NVERT * sizeof(float4));
    for (int j = threadIdx.x; j < NVERT; j += blockDim.x) {
        sv[j] = g_vs[j];
        sidx[j] = g_vsidx[j];
    }
    __syncthreads();

    float mnx, mny, mnz, dx, dy, dz;
    grid_params(mnx, mny, mnz, dx, dy, dz);
    float ivx = __fdiv_rn((float)GRES, dx);
    float ivy = __fdiv_rn((float)GRES, dy);
    float ivz = __fdiv_rn((float)GRES, dz);
    float* pout = out + 3 * NVERT;
    int lane = threadIdx.x & 31;
    int stride = gridDim.x * blockDim.x;

    // per-warp uniform base: n is a multiple of 32, so whenever a warp
    // iterates, ALL 32 lanes are in range -> warp collectives are safe.
    for (int base = blockIdx.x * blockDim.x + (threadIdx.x & ~31); base < n;
         base += stride) {
        int i = base + lane;
        float4 P = g_pts[i];                // coalesced
        float px = P.x, py = P.y, pz = P.z;
        int p = __float_as_int(P.w);
        float fx = (px - mnx) * ivx, fy = (py - mny) * ivy, fz = (pz - mnz) * ivz;
        int cx = min(max((int)floorf(fx), 0), GRES - 1);
        int cy = min(max((int)floorf(fy), 0), GRES - 1);
        int cz = min(max((int)floorf(fz), 0), GRES - 1);

        // ---- phase A: octant 2^3 box, bounds prefetched with MLP=8 ----
        float bestD = 3.402823466e38f;
        {
            int x0 = (fx - (float)cx > 0.5f) ? cx : cx - 1;
            int y0 = (fy - (float)cy > 0.5f) ? cy : cy - 1;
            int z0 = (fz - (float)cz > 0.5f) ? cz : cz - 1;
            x0 = max(x0, 0); int x1 = min(x0 + 1, GRES - 1); x0 = min(x0, x1);
            y0 = max(y0, 0); int y1 = min(y0 + 1, GRES - 1); y0 = min(y0, y1);
            z0 = max(z0, 0); int z1 = min(z0 + 1, GRES - 1); z0 = min(z0, z1);
            int r00 = (x0 * GRES + y0) * GRES;
            int r01 = (x0 * GRES + y1) * GRES;
            int r10 = (x1 * GRES + y0) * GRES;
            int r11 = (x1 * GRES + y1) * GRES;
            int s00 = v_off[r00 + z0], e00 = v_off[r00 + z1 + 1];
            int s01 = v_off[r01 + z0], e01 = v_off[r01 + z1 + 1];
            int s10 = v_off[r10 + z0], e10 = v_off[r10 + z1 + 1];
            int s11 = v_off[r11 + z0], e11 = v_off[r11 + z1 + 1];
            #pragma unroll 1
            for (int j = s00; j < e00; j++) {
                float4 V = sv[j];
                float ddx = px - 0.5f * V.x, ddy = py - 0.5f * V.y, ddz = pz - 0.5f * V.z;
                bestD = fminf(bestD, fmaf(ddz, ddz, fmaf(ddy, ddy, ddx * ddx)));
            }
            #pragma unroll 1
            for (int j = s01; j < e01; j++) {
                float4 V = sv[j];
                float ddx = px - 0.5f * V.x, ddy = py - 0.5f * V.y, ddz = pz - 0.5f * V.z;
                bestD = fminf(bestD, fmaf(ddz, ddz, fmaf(ddy, ddy, ddx * ddx)));
            }
            #pragma unroll 1
            for (int j = s10; j < e10; j++) {
                float4 V = sv[j];
                float ddx = px - 0.5f * V.x, ddy = py - 0.5f * V.y, ddz = pz - 0.5f * V.z;
                bestD = fminf(bestD, fmaf(ddz, ddz, fmaf(ddy, ddy, ddx * ddx)));
            }
            #pragma unroll 1
            for (int j = s11; j < e11; j++) {
                float4 V = sv[j];
                float ddx = px - 0.5f * V.x, ddy = py - 0.5f * V.y, ddz = pz - 0.5f * V.z;
                bestD = fminf(bestD, fmaf(ddz, ddz, fmaf(ddy, ddy, ddx * ddx)));
            }
        }

        bool brute = (bestD >= 3.0e38f);
        unsigned bm = __ballot_sync(FULLM, brute);

        float bd = 3.402823466e38f;
        int bi = 0x7FFFFFFF;

        if (!brute) {
            // ---- phase B: exact rescan, 1-ahead row prefetch (champion) ----
            float R = sqrtf(bestD + 1e-4f) + 1e-4f;
            int x0 = min(max((int)floorf((px - R - mnx) * ivx), 0), GRES - 1);
            int x1 = min(max((int)floorf((px + R - mnx) * ivx), 0), GRES - 1);
            int y0 = min(max((int)floorf((py - R - mny) * ivy), 0), GRES - 1);
            int y1 = min(max((int)floorf((py + R - mny) * ivy), 0), GRES - 1);
            int z0 = min(max((int)floorf((pz - R - mnz) * ivz), 0), GRES - 1);
            int z1 = min(max((int)floorf((pz + R - mnz) * ivz), 0), GRES - 1);
            int ny = y1 - y0 + 1;
            int nr = (x1 - x0 + 1) * ny;
            int ix = x0, iy = y0;
            int rowb = (ix * GRES + iy) * GRES;
            int sC = v_off[rowb + z0], eC = v_off[rowb + z1 + 1];
            for (int r = 0; r < nr; r++) {
                int nix = ix, niy = iy + 1;
                if (niy > y1) { niy = y0; nix = ix + 1; }
                int sN = 0, eN = 0;
                if (r + 1 < nr) {
                    int nb = (nix * GRES + niy) * GRES;
                    sN = v_off[nb + z0];
                    eN = v_off[nb + z1 + 1];
                }
                #pragma unroll 1
                for (int j = sC; j < eC; j++) {
                    float4 V = sv[j];
                    float t2 = fmaf(pz, V.z, fmaf(py, V.y, __fmul_rn(px, V.x)));
                    float d = __fsub_rn(V.w, t2);
                    int oi = sidx[j];
                    if (d < bd || (d == bd && oi < bi)) { bd = d; bi = oi; }
                }
                sC = sN; eC = eN; ix = nix; iy = niy;
            }
        }

        // ---- warp-cooperative exact brute force for empty-octant lanes ----
        while (bm) {
            int src = __ffs(bm) - 1;
            bm &= bm - 1;
            float qx = __shfl_sync(FULLM, px, src);
            float qy = __shfl_sync(FULLM, py, src);
            float qz = __shfl_sync(FULLM, pz, src);
            float bbd = 3.402823466e38f;
            int bbi = 0x7FFFFFFF;
            #pragma unroll 4
            for (int j = lane; j < NVERT; j += 32) {
                float4 V = sv[j];
                float t2 = fmaf(qz, V.z, fmaf(qy, V.y, __fmul_rn(qx, V.x)));
                float d = __fsub_rn(V.w, t2);
                int oi = sidx[j];
                if (d < bbd || (d == bbd && oi < bbi)) { bbd = d; bbi = oi; }
            }
            for (int o = 16; o; o >>= 1) {
                float od = __shfl_xor_sync(FULLM, bbd, o);
                int oi2 = __shfl_xor_sync(FULLM, bbi, o);
                if (od < bbd || (od == bbd && oi2 < bbi)) { bbd = od; bbi = oi2; }
            }
            if (lane == src) { bd = bbd; bi = bbi; }
        }
        pout[p] = (float)bi;
    }
}

// ---------------- launch ----------------
extern "C" void kernel_launch(void* const* d_in, const int* in_sizes, int n_in,
                              void* d_out, int out_size) {
    const float* xyz = (const float*)d_in[0];
    int n = in_sizes[0] / 3;
    float* out = (float*)d_out;

    int* d_ghist; cudaGetSymbolAddress((void**)&d_ghist, g_hist);
    int* d_goff;  cudaGetSymbolAddress((void**)&d_goff,  g_off);
    int* d_gcur;  cudaGetSymbolAddress((void**)&d_gcur,  g_cur);
    int* d_vhist; cudaGetSymbolAddress((void**)&d_vhist, v_hist);
    int* d_voff;  cudaGetSymbolAddress((void**)&d_voff,  v_off);
    int* d_vcur;  cudaGetSymbolAddress((void**)&d_vcur,  v_cur);
    unsigned int* d_mm; cudaGetSymbolAddress((void**)&d_mm, g_mm);

    // init via memset nodes
    cudaMemsetAsync(d_ghist, 0, NVOX * sizeof(int));
    cudaMemsetAsync(d_vhist, 0, NVOX * sizeof(int));
    cudaMemsetAsync(d_mm, 0xFF, 3 * sizeof(unsigned int));
    cudaMemsetAsync(d_mm + 3, 0x00, 3 * sizeof(unsigned int));

    k_minmax<<<148, 256>>>(xyz, n);
    k_vidhist<<<1024, 256>>>(xyz, n);
    k_scan_a<<<SCANB, 512>>>(d_ghist);
    k_scan_b<<<1, 512>>>(d_goff, n);
    k_scan_c<<<SCANB, 512>>>(d_ghist, d_goff, d_gcur);
    k_scatter<<<1024, 256>>>(xyz, n);
    k_select<<<NVERT, 128>>>(out, n);
    k_scan_a<<<SCANB, 512>>>(d_vhist);
    k_scan_b<<<1, 512>>>(d_voff, NVERT);
    k_scan_c<<<SCANB, 512>>>(d_vhist, d_voff, d_vcur);
    k_vscatter<<<16, 512>>>();

    int smem = NVERT * (int)sizeof(float4) + NVERT * (int)sizeof(unsigned short);
    cudaFuncSetAttribute(k_knn, cudaFuncAttributeMaxDynamicSharedMemorySize, smem);
    k_knn<<<148, 1024, smem>>>(out, n);
}

// round 16
// speedup vs baseline: 4.0082x; 3.9435x over previous
#include <cuda_runtime.h>

#define NVERT 8192
#define GRES 64
#define NVOX (GRES*GRES*GRES)   // 262144
#define NMAX 1048576
#define SCANB 512               // 512 blocks x 512 threads covers NVOX

// ---------------- scratch (device globals; no allocation) ----------------
__device__ unsigned int g_mm[6];        // sortable-uint min(x,y,z), max(x,y,z)
__device__ int g_hist[NVOX];
__device__ int g_off[NVOX + 1];
__device__ int g_cur[NVOX];
__device__ int g_bsum[SCANB];
__device__ int g_bbase[SCANB];
__device__ int g_vid[NMAX];
__device__ float4 g_pts[NMAX];          // voxel-sorted points {x,y,z,bits(origidx)}
__device__ float4 g_vert[NVERT];        // raw {x, y, z, |v|^2}
// vertex grid for pruned knn
__device__ int v_hist[NVOX];
__device__ int v_off[NVOX + 1];
__device__ int v_cur[NVOX];
__device__ int v_cell[NVERT];
__device__ float4 g_vs[NVERT];          // cell-sorted, prescaled {2x,2y,2z,|v|^2}
__device__ unsigned short g_vsidx[NVERT];

// monotone float<->uint mapping (min/max via integer atomics)
__device__ __forceinline__ unsigned f2o(float f) {
    unsigned b = __float_as_uint(f);
    return (b & 0x80000000u) ? ~b : (b | 0x80000000u);
}
__device__ __forceinline__ float o2f(unsigned o) {
    unsigned b = (o & 0x80000000u) ? (o & 0x7FFFFFFFu) : ~o;
    return __uint_as_float(b);
}

// shared helper: per-axis extent guards (must match k_vidhist exactly)
__device__ __forceinline__ void grid_params(float& mnx, float& mny, float& mnz,
                                            float& dx, float& dy, float& dz) {
    mnx = o2f(g_mm[0]); mny = o2f(g_mm[1]); mnz = o2f(g_mm[2]);
    float exx = __fsub_rn(o2f(g_mm[3]), mnx);
    float exy = __fsub_rn(o2f(g_mm[4]), mny);
    float exz = __fsub_rn(o2f(g_mm[5]), mnz);
    dx = exx > 0.f ? exx : 1.f;
    dy = exy > 0.f ? exy : 1.f;
    dz = exz > 0.f ? exz : 1.f;
}

// ---------------- 2. global min/max per coordinate ----------------
__global__ void k_minmax(const float* __restrict__ xyz, int n) {
    float mnx = 3.402823466e38f, mny = mnx, mnz = mnx;
    float mxx = -3.402823466e38f, mxy = mxx, mxz = mxx;
    for (int i = blockIdx.x * blockDim.x + threadIdx.x; i < n;
         i += gridDim.x * blockDim.x) {
        float x = xyz[3 * i], y = xyz[3 * i + 1], z = xyz[3 * i + 2];
        mnx = fminf(mnx, x); mny = fminf(mny, y); mnz = fminf(mnz, z);
        mxx = fmaxf(mxx, x); mxy = fmaxf(mxy, y); mxz = fmaxf(mxz, z);
    }
    for (int o = 16; o; o >>= 1) {
        mnx = fminf(mnx, __shfl_xor_sync(0xFFFFFFFFu, mnx, o));
        mny = fminf(mny, __shfl_xor_sync(0xFFFFFFFFu, mny, o));
        mnz = fminf(mnz, __shfl_xor_sync(0xFFFFFFFFu, mnz, o));
        mxx = fmaxf(mxx, __shfl_xor_sync(0xFFFFFFFFu, mxx, o));
        mxy = fmaxf(mxy, __shfl_xor_sync(0xFFFFFFFFu, mxy, o));
        mxz = fmaxf(mxz, __shfl_xor_sync(0xFFFFFFFFu, mxz, o));
    }
    if ((threadIdx.x & 31) == 0) {
        atomicMin(&g_mm[0], f2o(mnx));
        atomicMin(&g_mm[1], f2o(mny));
        atomicMin(&g_mm[2], f2o(mnz));
        atomicMax(&g_mm[3], f2o(mxx));
        atomicMax(&g_mm[4], f2o(mxy));
        atomicMax(&g_mm[5], f2o(mxz));
    }
}

// ---------------- 3. voxel id + histogram (reciprocal-hoisted division) ----
__global__ void k_vidhist(const float* __restrict__ xyz, int n) {
    float mnx, mny, mnz, dx, dy, dz;
    grid_params(mnx, mny, mnz, dx, dy, dz);
    float rx = __fdiv_rn(1.0f, dx);
    float ry = __fdiv_rn(1.0f, dy);
    float rz = __fdiv_rn(1.0f, dz);
    const float HI = (float)(1.0 - 1e-6);
    for (int i = blockIdx.x * blockDim.x + threadIdx.x; i < n;
         i += gridDim.x * blockDim.x) {
        float ux = __fmul_rn(__fsub_rn(xyz[3 * i],     mnx), rx);
        float uy = __fmul_rn(__fsub_rn(xyz[3 * i + 1], mny), ry);
        float uz = __fmul_rn(__fsub_rn(xyz[3 * i + 2], mnz), rz);
        ux = fminf(fmaxf(ux, 0.f), HI);
        uy = fminf(fmaxf(uy, 0.f), HI);
        uz = fminf(fmaxf(uz, 0.f), HI);
        int vx = (int)floorf(__fmul_rn(ux, (float)GRES));
        int vy = (int)floorf(__fmul_rn(uy, (float)GRES));
        int vz = (int)floorf(__fmul_rn(uz, (float)GRES));
        int vid = (vx * GRES + vy) * GRES + vz;
        g_vid[i] = vid;
        atomicAdd(&g_hist[vid], 1);
    }
}

// ---------------- 4. generic exclusive scan over NVOX (3 kernels) ----------
__global__ void k_scan_a(const int* __restrict__ hist) {
    __shared__ int sh[512];
    int i = blockIdx.x * 512 + threadIdx.x;
    sh[threadIdx.x] = hist[i];
    __syncthreads();
    for (int off = 256; off; off >>= 1) {
        if (threadIdx.x < off) sh[threadIdx.x] += sh[threadIdx.x + off];
        __syncthreads();
    }
    if (threadIdx.x == 0) g_bsum[blockIdx.x] = sh[0];
}
__global__ void k_scan_b(int* __restrict__ off, int total) {
    __shared__ int sh[512];
    int v = g_bsum[threadIdx.x];
    sh[threadIdx.x] = v;
    __syncthreads();
    for (int o = 1; o < 512; o <<= 1) {
        int t = (threadIdx.x >= o) ? sh[threadIdx.x - o] : 0;
        __syncthreads();
        sh[threadIdx.x] += t;
        __syncthreads();
    }
    g_bbase[threadIdx.x] = sh[threadIdx.x] - v;
    if (threadIdx.x == 0) off[NVOX] = total;
}
__global__ void k_scan_c(const int* __restrict__ hist, int* __restrict__ off,
                         int* __restrict__ cur) {
    __shared__ int sh[512];
    int i = blockIdx.x * 512 + threadIdx.x;
    int v = hist[i];
    sh[threadIdx.x] = v;
    __syncthreads();
    for (int o = 1; o < 512; o <<= 1) {
        int t = (threadIdx.x >= o) ? sh[threadIdx.x - o] : 0;
        __syncthreads();
        sh[threadIdx.x] += t;
        __syncthreads();
    }
    int excl = sh[threadIdx.x] - v + g_bbase[blockIdx.x];
    off[i] = excl;
    cur[i] = excl;
}

// ---------------- 5. counting-sort scatter: packed point records -----------
__global__ void k_scatter(const float* __restrict__ xyz, int n) {
    for (int i = blockIdx.x * blockDim.x + threadIdx.x; i < n;
         i += gridDim.x * blockDim.x) {
        int v = g_vid[i];
        int pos = atomicAdd(&g_cur[v], 1);
        g_pts[pos] = make_float4(xyz[3 * i], xyz[3 * i + 1], xyz[3 * i + 2],
                                 __int_as_float(i));
    }
}

// ---------------- 6. stable selection of 8192 vertices (+ vertex binning) --
// sel per f32 jnp.linspace: delta = RN((n-1)/8191); s = floor(RN(q*delta)).
__global__ void k_select(float* __restrict__ out, int n) {
    __shared__ int sb[4096];
    __shared__ int info[3];
    int q = blockIdx.x;
    if (threadIdx.x == 0) {
        float delta = __fdiv_rn((float)(n - 1), (float)(NVERT - 1));
        float fv = __fmul_rn((float)q, delta);
        int s = (int)floorf(fv);
        int lo = 0, hi = NVOX;
        while (hi - lo > 1) {
            int mid = (lo + hi) >> 1;
            if (g_off[mid] <= s) lo = mid; else hi = mid;
        }
        info[0] = g_off[lo];
        info[1] = g_off[lo + 1] - g_off[lo];
        info[2] = s - g_off[lo];
    }
    __syncthreads();
    int base = info[0], m = info[1], r = info[2];

    float mnx, mny, mnz, dx, dy, dz;
    grid_params(mnx, mny, mnz, dx, dy, dz);
    float ivx = __fdiv_rn((float)GRES, dx);
    float ivy = __fdiv_rn((float)GRES, dy);
    float ivz = __fdiv_rn((float)GRES, dz);

    if (m <= 4096) {
        for (int j = threadIdx.x; j < m; j += blockDim.x)
            sb[j] = __float_as_int(g_pts[base + j].w);
        __syncthreads();
        for (int j = threadIdx.x; j < m; j += blockDim.x) {
            int x = sb[j], c = 0;
            for (int t = 0; t < m; t++) c += (sb[t] < x);
            if (c == r) {
                float4 P = g_pts[base + j];
                out[3 * q] = P.x; out[3 * q + 1] = P.y; out[3 * q + 2] = P.z;
                float vn = __fadd_rn(__fadd_rn(__fmul_rn(P.x, P.x), __fmul_rn(P.y, P.y)),
                                     __fmul_rn(P.z, P.z));
                g_vert[q] = make_float4(P.x, P.y, P.z, vn);
                int cx = min(max((int)floorf((P.x - mnx) * ivx), 0), GRES - 1);
                int cy = min(max((int)floorf((P.y - mny) * ivy), 0), GRES - 1);
                int cz = min(max((int)floorf((P.z - mnz) * ivz), 0), GRES - 1);
                int cell = (cx * GRES + cy) * GRES + cz;
                v_cell[q] = cell;
                atomicAdd(&v_hist[cell], 1);
            }
        }
    } else {
        for (int j = threadIdx.x; j < m; j += blockDim.x) {
            int x = __float_as_int(g_pts[base + j].w), c = 0;
            for (int t = 0; t < m; t++)
                c += (__float_as_int(g_pts[base + t].w) < x);
            if (c == r) {
                float4 P = g_pts[base + j];
                out[3 * q] = P.x; out[3 * q + 1] = P.y; out[3 * q + 2] = P.z;
                float vn = __fadd_rn(__fadd_rn(__fmul_rn(P.x, P.x), __fmul_rn(P.y, P.y)),
                                     __fmul_rn(P.z, P.z));
                g_vert[q] = make_float4(P.x, P.y, P.z, vn);
                int cx = min(max((int)floorf((P.x - mnx) * ivx), 0), GRES - 1);
                int cy = min(max((int)floorf((P.y - mny) * ivy), 0), GRES - 1);
                int cz = min(max((int)floorf((P.z - mnz) * ivz), 0), GRES - 1);
                int cell = (cx * GRES + cy) * GRES + cz;
                v_cell[q] = cell;
                atomicAdd(&v_hist[cell], 1);
            }
        }
    }
}

// ---------------- 6c. scatter vertices (prescaled by 2) --------------------
__global__ void k_vscatter() {
    int q = blockIdx.x * blockDim.x + threadIdx.x;
    if (q >= NVERT) return;
    int c = v_cell[q];
    int pos = atomicAdd(&v_cur[c], 1);
    float4 v = g_vert[q];
    g_vs[pos] = make_float4(2.0f * v.x, 2.0f * v.y, 2.0f * v.z, v.w);
    g_vsidx[pos] = (unsigned short)q;
}

// exact reference-formula eval + lexicographic (d, oi) min update
#define EVAL_EXACT(J)                                                          \
    do {                                                                       \
        float4 V = sv[J];                                                      \
        float t2 = fmaf(pz, V.z, fmaf(py, V.y, __fmul_rn(px, V.x)));           \
        float d = __fsub_rn(V.w, t2);                                          \
        int oi = sidx[J];                                                      \
        if (d < bd || (d == bd && oi < bi)) { bd = d; bi = oi; }               \
    } while (0)

// ---------------- 7. grid-pruned 1-NN; phase-B bounds fully MLP-batched ----
// Phase A: octant 2^3 box, all 8 v_off LDGs issued up-front (MLP=8).
// Phase B: ALL row bounds (up to 9 rows) prefetched into registers in ONE
// unrolled MLP batch before any eval — collapses the nr x ~230cyc serial
// scoreboard chain (the real bottleneck; knn ran at ~3% issue efficiency)
// to a single ~260cyc round trip. Rows beyond 9: old 1-ahead serial loop.
// Eval set, formula, and (d, oi) comparator identical to the 493us champion.
__global__ void __launch_bounds__(1024, 1)
k_knn(float* __restrict__ out, int n) {
    extern __shared__ char smem[];
    float4* sv = (float4*)smem;                         // 8192 * 16B
    unsigned short* sidx = (unsigned short*)(smem + NVERT * sizeof(float4));
    for (int j = threadIdx.x; j < NVERT; j += blockDim.x) {
        sv[j] = g_vs[j];
        sidx[j] = g_vsidx[j];
    }
    __syncthreads();

    float mnx, mny, mnz, dx, dy, dz;
    grid_params(mnx, mny, mnz, dx, dy, dz);
    float ivx = __fdiv_rn((float)GRES, dx);
    float ivy = __fdiv_rn((float)GRES, dy);
    float ivz = __fdiv_rn((float)GRES, dz);
    float* pout = out + 3 * NVERT;

    for (int i = blockIdx.x * blockDim.x + threadIdx.x; i < n;
         i += gridDim.x * blockDim.x) {
        float4 P = g_pts[i];                // coalesced
        float px = P.x, py = P.y, pz = P.z;
        int p = __float_as_int(P.w);
        float fx = (px - mnx) * ivx, fy = (py - mny) * ivy, fz = (pz - mnz) * ivz;
        int cx = min(max((int)floorf(fx), 0), GRES - 1);
        int cy = min(max((int)floorf(fy), 0), GRES - 1);
        int cz = min(max((int)floorf(fz), 0), GRES - 1);

        // ---- phase A: octant 2^3 box, bounds prefetched with MLP=8 ----
        float bestD = 3.402823466e38f;
        {
            int x0 = (fx - (float)cx > 0.5f) ? cx : cx - 1;
            int y0 = (fy - (float)cy > 0.5f) ? cy : cy - 1;
            int z0 = (fz - (float)cz > 0.5f) ? cz : cz - 1;
            x0 = max(x0, 0); int x1 = min(x0 + 1, GRES - 1); x0 = min(x0, x1);
            y0 = max(y0, 0); int y1 = min(y0 + 1, GRES - 1); y0 = min(y0, y1);
            z0 = max(z0, 0); int z1 = min(z0 + 1, GRES - 1); z0 = min(z0, z1);
            int r00 = (x0 * GRES + y0) * GRES;
            int r01 = (x0 * GRES + y1) * GRES;
            int r10 = (x1 * GRES + y0) * GRES;
            int r11 = (x1 * GRES + y1) * GRES;
            int s00 = v_off[r00 + z0], e00 = v_off[r00 + z1 + 1];
            int s01 = v_off[r01 + z0], e01 = v_off[r01 + z1 + 1];
            int s10 = v_off[r10 + z0], e10 = v_off[r10 + z1 + 1];
            int s11 = v_off[r11 + z0], e11 = v_off[r11 + z1 + 1];
            #pragma unroll 1
            for (int j = s00; j < e00; j++) {
                float4 V = sv[j];
                float ddx = px - 0.5f * V.x, ddy = py - 0.5f * V.y, ddz = pz - 0.5f * V.z;
                bestD = fminf(bestD, fmaf(ddz, ddz, fmaf(ddy, ddy, ddx * ddx)));
            }
            #pragma unroll 1
            for (int j = s01; j < e01; j++) {
                float4 V = sv[j];
                float ddx = px - 0.5f * V.x, ddy = py - 0.5f * V.y, ddz = pz - 0.5f * V.z;
                bestD = fminf(bestD, fmaf(ddz, ddz, fmaf(ddy, ddy, ddx * ddx)));
            }
            #pragma unroll 1
            for (int j = s10; j < e10; j++) {
                float4 V = sv[j];
                float ddx = px - 0.5f * V.x, ddy = py - 0.5f * V.y, ddz = pz - 0.5f * V.z;
                bestD = fminf(bestD, fmaf(ddz, ddz, fmaf(ddy, ddy, ddx * ddx)));
            }
            #pragma unroll 1
            for (int j = s11; j < e11; j++) {
                float4 V = sv[j];
                float ddx = px - 0.5f * V.x, ddy = py - 0.5f * V.y, ddz = pz - 0.5f * V.z;
                bestD = fminf(bestD, fmaf(ddz, ddz, fmaf(ddy, ddy, ddx * ddx)));
            }
        }
        // fallback: expanding boxes until any vertex found (rare)
        if (bestD >= 3.0e38f) {
            for (int w = 1; w < GRES; w++) {
                int x0 = max(cx - w, 0), x1 = min(cx + w, GRES - 1);
                int y0 = max(cy - w, 0), y1 = min(cy + w, GRES - 1);
                int z0 = max(cz - w, 0), z1 = min(cz + w, GRES - 1);
                for (int ix = x0; ix <= x1; ix++)
                    for (int iy = y0; iy <= y1; iy++) {
                        int row = (ix * GRES + iy) * GRES;
                        int s = v_off[row + z0];
                        int e = v_off[row + z1 + 1];
                        for (int j = s; j < e; j++) {
                            float4 V = sv[j];
                            float ddx = px - 0.5f * V.x, ddy = py - 0.5f * V.y, ddz = pz - 0.5f * V.z;
                            bestD = fminf(bestD, fmaf(ddz, ddz, fmaf(ddy, ddy, ddx * ddx)));
                        }
                    }
                if (bestD < 3.0e38f) break;
            }
        }

        // ---- phase B: exact rescan of sphere box, bounds MLP-batched ----
        float R = sqrtf(bestD + 1e-4f) + 1e-4f;
        int x0 = min(max((int)floorf((px - R - mnx) * ivx), 0), GRES - 1);
        int x1 = min(max((int)floorf((px + R - mnx) * ivx), 0), GRES - 1);
        int y0 = min(max((int)floorf((py - R - mny) * ivy), 0), GRES - 1);
        int y1 = min(max((int)floorf((py + R - mny) * ivy), 0), GRES - 1);
        int z0 = min(max((int)floorf((pz - R - mnz) * ivz), 0), GRES - 1);
        int z1 = min(max((int)floorf((pz + R - mnz) * ivz), 0), GRES - 1);

        float bd = 3.402823466e38f;
        int bi = 0x7FFFFFFF;
        int nr = (x1 - x0 + 1) * (y1 - y0 + 1);

        const int NPF = 9;
        int sR[NPF], eR[NPF];
        int ix = x0, iy = y0;
        #pragma unroll
        for (int r = 0; r < NPF; r++) {
            if (r < nr) {
                int rb = (ix * GRES + iy) * GRES;
                sR[r] = v_off[rb + z0];
                eR[r] = v_off[rb + z1 + 1];
            } else { sR[r] = 0; eR[r] = 0; }
            iy++; if (iy > y1) { iy = y0; ix++; }
        }
        #pragma unroll
        for (int r = 0; r < NPF; r++) {
            #pragma unroll 1
            for (int j = sR[r]; j < eR[r]; j++) EVAL_EXACT(j);
        }
        if (nr > NPF) {
            // leftover rows: serial 1-ahead (ix/iy already point at row NPF)
            int rb = (ix * GRES + iy) * GRES;
            int sC = v_off[rb + z0], eC = v_off[rb + z1 + 1];
            for (int r = NPF; r < nr; r++) {
                int nix = ix, niy = iy + 1;
                if (niy > y1) { niy = y0; nix = ix + 1; }
                int sN = 0, eN = 0;
                if (r + 1 < nr) {
                    int nb = (nix * GRES + niy) * GRES;
                    sN = v_off[nb + z0];
                    eN = v_off[nb + z1 + 1];
                }
                #pragma unroll 1
                for (int j = sC; j < eC; j++) EVAL_EXACT(j);
                sC = sN; eC = eN; ix = nix; iy = niy;
            }
        }
        pout[p] = (float)bi;
    }
}

// ---------------- launch ----------------
extern "C" void kernel_launch(void* const* d_in, const int* in_sizes, int n_in,
                              void* d_out, int out_size) {
    const float* xyz = (const float*)d_in[0];
    int n = in_sizes[0] / 3;
    float* out = (float*)d_out;

    int* d_ghist; cudaGetSymbolAddress((void**)&d_ghist, g_hist);
    int* d_goff;  cudaGetSymbolAddress((void**)&d_goff,  g_off);
    int* d_gcur;  cudaGetSymbolAddress((void**)&d_gcur,  g_cur);
    int* d_vhist; cudaGetSymbolAddress((void**)&d_vhist, v_hist);
    int* d_voff;  cudaGetSymbolAddress((void**)&d_voff,  v_off);
    int* d_vcur;  cudaGetSymbolAddress((void**)&d_vcur,  v_cur);
    unsigned int* d_mm; cudaGetSymbolAddress((void**)&d_mm, g_mm);

    // init via memset nodes
    cudaMemsetAsync(d_ghist, 0, NVOX * sizeof(int));
    cudaMemsetAsync(d_vhist, 0, NVOX * sizeof(int));
    cudaMemsetAsync(d_mm, 0xFF, 3 * sizeof(unsigned int));
    cudaMemsetAsync(d_mm + 3, 0x00, 3 * sizeof(unsigned int));

    k_minmax<<<148, 256>>>(xyz, n);
    k_vidhist<<<1024, 256>>>(xyz, n);
    k_scan_a<<<SCANB, 512>>>(d_ghist);
    k_scan_b<<<1, 512>>>(d_goff, n);
    k_scan_c<<<SCANB, 512>>>(d_ghist, d_goff, d_gcur);
    k_scatter<<<1024, 256>>>(xyz, n);
    k_select<<<NVERT, 128>>>(out, n);
    k_scan_a<<<SCANB, 512>>>(d_vhist);
    k_scan_b<<<1, 512>>>(d_voff, NVERT);
    k_scan_c<<<SCANB, 512>>>(d_vhist, d_voff, d_vcur);
    k_vscatter<<<16, 512>>>();

    int smem = NVERT * (int)sizeof(float4) + NVERT * (int)sizeof(unsigned short);
    cudaFuncSetAttribute(k_knn, cudaFuncAttributeMaxDynamicSharedMemorySize, smem);
    k_knn<<<148, 1024, smem>>>(out, n);
}

// round 17
// speedup vs baseline: 4.5018x; 1.1231x over previous
#include <cuda_runtime.h>

#define NVERT 8192
#define GRES 64
#define NVOX (GRES*GRES*GRES)   // 262144
#define GRESC 16
#define NVOXC (GRESC*GRESC*GRESC) // 4096
#define NMAX 1048576
#define SCANB 512               // 512 blocks x 512 threads covers NVOX
#define FULLM 0xFFFFFFFFu

// ---------------- scratch (device globals; no allocation) ----------------
__device__ unsigned int g_mm[6];        // sortable-uint min(x,y,z), max(x,y,z)
__device__ int g_hist[NVOX];
__device__ int g_off[NVOX + 1];
__device__ int g_cur[NVOX];
__device__ int g_bsum[SCANB];
__device__ int g_bbase[SCANB];
__device__ int g_vid[NMAX];
__device__ float4 g_pts[NMAX];          // voxel-sorted points {x,y,z,bits(origidx)}
__device__ float4 g_vert[NVERT];        // raw {x, y, z, |v|^2}
// vertex grid for pruned knn
__device__ int v_hist[NVOX];
__device__ int v_off[NVOX + 1];
__device__ int v_cur[NVOX];
__device__ int v_cell[NVERT];
__device__ float4 g_vs[NVERT];          // cell-sorted, prescaled {2x,2y,2z,|v|^2}
__device__ unsigned short g_vsidx[NVERT];
__device__ float g_ccdist[NVOXC];       // coarse-cell NN-radius upper bound

// monotone float<->uint mapping (min/max via integer atomics)
__device__ __forceinline__ unsigned f2o(float f) {
    unsigned b = __float_as_uint(f);
    return (b & 0x80000000u) ? ~b : (b | 0x80000000u);
}
__device__ __forceinline__ float o2f(unsigned o) {
    unsigned b = (o & 0x80000000u) ? (o & 0x7FFFFFFFu) : ~o;
    return __uint_as_float(b);
}

// shared helper: per-axis extent guards (must match k_vidhist exactly)
__device__ __forceinline__ void grid_params(float& mnx, float& mny, float& mnz,
                                            float& dx, float& dy, float& dz) {
    mnx = o2f(g_mm[0]); mny = o2f(g_mm[1]); mnz = o2f(g_mm[2]);
    float exx = __fsub_rn(o2f(g_mm[3]), mnx);
    float exy = __fsub_rn(o2f(g_mm[4]), mny);
    float exz = __fsub_rn(o2f(g_mm[5]), mnz);
    dx = exx > 0.f ? exx : 1.f;
    dy = exy > 0.f ? exy : 1.f;
    dz = exz > 0.f ? exz : 1.f;
}

// ---------------- 2. global min/max per coordinate ----------------
__global__ void k_minmax(const float* __restrict__ xyz, int n) {
    float mnx = 3.402823466e38f, mny = mnx, mnz = mnx;
    float mxx = -3.402823466e38f, mxy = mxx, mxz = mxx;
    for (int i = blockIdx.x * blockDim.x + threadIdx.x; i < n;
         i += gridDim.x * blockDim.x) {
        float x = xyz[3 * i], y = xyz[3 * i + 1], z = xyz[3 * i + 2];
        mnx = fminf(mnx, x); mny = fminf(mny, y); mnz = fminf(mnz, z);
        mxx = fmaxf(mxx, x); mxy = fmaxf(mxy, y); mxz = fmaxf(mxz, z);
    }
    for (int o = 16; o; o >>= 1) {
        mnx = fminf(mnx, __shfl_xor_sync(FULLM, mnx, o));
        mny = fminf(mny, __shfl_xor_sync(FULLM, mny, o));
        mnz = fminf(mnz, __shfl_xor_sync(FULLM, mnz, o));
        mxx = fmaxf(mxx, __shfl_xor_sync(FULLM, mxx, o));
        mxy = fmaxf(mxy, __shfl_xor_sync(FULLM, mxy, o));
        mxz = fmaxf(mxz, __shfl_xor_sync(FULLM, mxz, o));
    }
    if ((threadIdx.x & 31) == 0) {
        atomicMin(&g_mm[0], f2o(mnx));
        atomicMin(&g_mm[1], f2o(mny));
        atomicMin(&g_mm[2], f2o(mnz));
        atomicMax(&g_mm[3], f2o(mxx));
        atomicMax(&g_mm[4], f2o(mxy));
        atomicMax(&g_mm[5], f2o(mxz));
    }
}

// ---------------- 3. voxel id + histogram (reciprocal-hoisted division) ----
__global__ void k_vidhist(const float* __restrict__ xyz, int n) {
    float mnx, mny, mnz, dx, dy, dz;
    grid_params(mnx, mny, mnz, dx, dy, dz);
    float rx = __fdiv_rn(1.0f, dx);
    float ry = __fdiv_rn(1.0f, dy);
    float rz = __fdiv_rn(1.0f, dz);
    const float HI = (float)(1.0 - 1e-6);
    for (int i = blockIdx.x * blockDim.x + threadIdx.x; i < n;
         i += gridDim.x * blockDim.x) {
        float ux = __fmul_rn(__fsub_rn(xyz[3 * i],     mnx), rx);
        float uy = __fmul_rn(__fsub_rn(xyz[3 * i + 1], mny), ry);
        float uz = __fmul_rn(__fsub_rn(xyz[3 * i + 2], mnz), rz);
        ux = fminf(fmaxf(ux, 0.f), HI);
        uy = fminf(fmaxf(uy, 0.f), HI);
        uz = fminf(fmaxf(uz, 0.f), HI);
        int vx = (int)floorf(__fmul_rn(ux, (float)GRES));
        int vy = (int)floorf(__fmul_rn(uy, (float)GRES));
        int vz = (int)floorf(__fmul_rn(uz, (float)GRES));
        int vid = (vx * GRES + vy) * GRES + vz;
        g_vid[i] = vid;
        atomicAdd(&g_hist[vid], 1);
    }
}

// ---------------- 4. generic exclusive scan over NVOX (3 kernels) ----------
__global__ void k_scan_a(const int* __restrict__ hist) {
    __shared__ int sh[512];
    int i = blockIdx.x * 512 + threadIdx.x;
    sh[threadIdx.x] = hist[i];
    __syncthreads();
    for (int off = 256; off; off >>= 1) {
        if (threadIdx.x < off) sh[threadIdx.x] += sh[threadIdx.x + off];
        __syncthreads();
    }
    if (threadIdx.x == 0) g_bsum[blockIdx.x] = sh[0];
}
__global__ void k_scan_b(int* __restrict__ off, int total) {
    __shared__ int sh[512];
    int v = g_bsum[threadIdx.x];
    sh[threadIdx.x] = v;
    __syncthreads();
    for (int o = 1; o < 512; o <<= 1) {
        int t = (threadIdx.x >= o) ? sh[threadIdx.x - o] : 0;
        __syncthreads();
        sh[threadIdx.x] += t;
        __syncthreads();
    }
    g_bbase[threadIdx.x] = sh[threadIdx.x] - v;
    if (threadIdx.x == 0) off[NVOX] = total;
}
__global__ void k_scan_c(const int* __restrict__ hist, int* __restrict__ off,
                         int* __restrict__ cur) {
    __shared__ int sh[512];
    int i = blockIdx.x * 512 + threadIdx.x;
    int v = hist[i];
    sh[threadIdx.x] = v;
    __syncthreads();
    for (int o = 1; o < 512; o <<= 1) {
        int t = (threadIdx.x >= o) ? sh[threadIdx.x - o] : 0;
        __syncthreads();
        sh[threadIdx.x] += t;
        __syncthreads();
    }
    int excl = sh[threadIdx.x] - v + g_bbase[blockIdx.x];
    off[i] = excl;
    cur[i] = excl;
}

// ---------------- 5. counting-sort scatter: packed point records -----------
__global__ void k_scatter(const float* __restrict__ xyz, int n) {
    for (int i = blockIdx.x * blockDim.x + threadIdx.x; i < n;
         i += gridDim.x * blockDim.x) {
        int v = g_vid[i];
        int pos = atomicAdd(&g_cur[v], 1);
        g_pts[pos] = make_float4(xyz[3 * i], xyz[3 * i + 1], xyz[3 * i + 2],
                                 __int_as_float(i));
    }
}

// ---------------- 6. stable selection of 8192 vertices (+ vertex binning) --
// sel per f32 jnp.linspace: delta = RN((n-1)/8191); s = floor(RN(q*delta)).
__global__ void k_select(float* __restrict__ out, int n) {
    __shared__ int sb[4096];
    __shared__ int info[3];
    int q = blockIdx.x;
    if (threadIdx.x == 0) {
        float delta = __fdiv_rn((float)(n - 1), (float)(NVERT - 1));
        float fv = __fmul_rn((float)q, delta);
        int s = (int)floorf(fv);
        int lo = 0, hi = NVOX;
        while (hi - lo > 1) {
            int mid = (lo + hi) >> 1;
            if (g_off[mid] <= s) lo = mid; else hi = mid;
        }
        info[0] = g_off[lo];
        info[1] = g_off[lo + 1] - g_off[lo];
        info[2] = s - g_off[lo];
    }
    __syncthreads();
    int base = info[0], m = info[1], r = info[2];

    float mnx, mny, mnz, dx, dy, dz;
    grid_params(mnx, mny, mnz, dx, dy, dz);
    float ivx = __fdiv_rn((float)GRES, dx);
    float ivy = __fdiv_rn((float)GRES, dy);
    float ivz = __fdiv_rn((float)GRES, dz);

    if (m <= 4096) {
        for (int j = threadIdx.x; j < m; j += blockDim.x)
            sb[j] = __float_as_int(g_pts[base + j].w);
        __syncthreads();
        for (int j = threadIdx.x; j < m; j += blockDim.x) {
            int x = sb[j], c = 0;
            for (int t = 0; t < m; t++) c += (sb[t] < x);
            if (c == r) {
                float4 P = g_pts[base + j];
                out[3 * q] = P.x; out[3 * q + 1] = P.y; out[3 * q + 2] = P.z;
                float vn = __fadd_rn(__fadd_rn(__fmul_rn(P.x, P.x), __fmul_rn(P.y, P.y)),
                                     __fmul_rn(P.z, P.z));
                g_vert[q] = make_float4(P.x, P.y, P.z, vn);
                int cx = min(max((int)floorf((P.x - mnx) * ivx), 0), GRES - 1);
                int cy = min(max((int)floorf((P.y - mny) * ivy), 0), GRES - 1);
                int cz = min(max((int)floorf((P.z - mnz) * ivz), 0), GRES - 1);
                int cell = (cx * GRES + cy) * GRES + cz;
                v_cell[q] = cell;
                atomicAdd(&v_hist[cell], 1);
            }
        }
    } else {
        for (int j = threadIdx.x; j < m; j += blockDim.x) {
            int x = __float_as_int(g_pts[base + j].w), c = 0;
            for (int t = 0; t < m; t++)
                c += (__float_as_int(g_pts[base + t].w) < x);
            if (c == r) {
                float4 P = g_pts[base + j];
                out[3 * q] = P.x; out[3 * q + 1] = P.y; out[3 * q + 2] = P.z;
                float vn = __fadd_rn(__fadd_rn(__fmul_rn(P.x, P.x), __fmul_rn(P.y, P.y)),
                                     __fmul_rn(P.z, P.z));
                g_vert[q] = make_float4(P.x, P.y, P.z, vn);
                int cx = min(max((int)floorf((P.x - mnx) * ivx), 0), GRES - 1);
                int cy = min(max((int)floorf((P.y - mny) * ivy), 0), GRES - 1);
                int cz = min(max((int)floorf((P.z - mnz) * ivz), 0), GRES - 1);
                int cell = (cx * GRES + cy) * GRES + cz;
                v_cell[q] = cell;
                atomicAdd(&v_hist[cell], 1);
            }
        }
    }
}

// ---------------- 6c. scatter vertices (prescaled by 2) --------------------
__global__ void k_vscatter() {
    int q = blockIdx.x * blockDim.x + threadIdx.x;
    if (q >= NVERT) return;
    int c = v_cell[q];
    int pos = atomicAdd(&v_cur[c], 1);
    float4 v = g_vert[q];
    g_vs[pos] = make_float4(2.0f * v.x, 2.0f * v.y, 2.0f * v.z, v.w);
    g_vsidx[pos] = (unsigned short)q;
}

// ---------------- 6d. coarse-cell NN-radius upper bound --------------------
// For each 16^3 coarse cell: R_ub = dist(cell center, nearest vertex)
//  + half cell diagonal + 1e-3. Any point inside the cell has its NN
// within R_ub (triangle inequality). One warp per cell, coalesced evals.
__global__ void k_ccdist() {
    int warp = (blockIdx.x * blockDim.x + threadIdx.x) >> 5;
    int lane = threadIdx.x & 31;
    if (warp >= NVOXC) return;
    float mnx, mny, mnz, dx, dy, dz;
    grid_params(mnx, mny, mnz, dx, dy, dz);
    float cdx = dx / (float)GRESC, cdy = dy / (float)GRESC, cdz = dz / (float)GRESC;
    int ccx = warp / (GRESC * GRESC);
    int ccy = (warp / GRESC) % GRESC;
    int ccz = warp % GRESC;
    float cxw = mnx + ((float)ccx + 0.5f) * cdx;
    float cyw = mny + ((float)ccy + 0.5f) * cdy;
    float czw = mnz + ((float)ccz + 0.5f) * cdz;
    float best = 3.402823466e38f;
    for (int j = lane; j < NVERT; j += 32) {
        float4 v = g_vert[j];
        float ax = cxw - v.x, ay = cyw - v.y, az = czw - v.z;
        best = fminf(best, fmaf(az, az, fmaf(ay, ay, ax * ax)));
    }
    for (int o = 16; o; o >>= 1)
        best = fminf(best, __shfl_xor_sync(FULLM, best, o));
    if (lane == 0) {
        float hd = 0.5f * sqrtf(cdx * cdx + cdy * cdy + cdz * cdz);
        g_ccdist[warp] = sqrtf(best) + hd + 1e-3f;
    }
}

// exact reference-formula eval + lexicographic (d, oi) min update
#define EVAL_EXACT(J)                                                          \
    do {                                                                       \
        float4 V = sv[J];                                                      \
        float t2 = fmaf(pz, V.z, fmaf(py, V.y, __fmul_rn(px, V.x)));           \
        float d = __fsub_rn(V.w, t2);                                          \
        int oi = sidx[J];                                                      \
        if (d < bd || (d == bd && oi < bi)) { bd = d; bi = oi; }               \
    } while (0)

// ---------------- 7. grid-pruned 1-NN; ccdist replaces the crawl -----------
// Dense path identical to the 490us champion. Empty-octant points (the
// MAJORITY outside the dense core — vertex density is only ~0.08/cell!)
// skip the serialized expanding crawl: read the coarse-cell radius bound
// from shared and scan the guaranteed-covering sphere box ONCE with the
// exact formula, row bounds batch-prefetched 16 at a time (MLP).
__global__ void __launch_bounds__(1024, 1)
k_knn(float* __restrict__ out, int n) {
    extern __shared__ char smem[];
    float4* sv = (float4*)smem;                           // 8192*16 = 128K
    unsigned short* sidx = (unsigned short*)(smem + NVERT * sizeof(float4)); // 16K
    float* scc = (float*)(smem + NVERT * sizeof(float4) + NVERT * sizeof(unsigned short)); // 16K
    for (int j = threadIdx.x; j < NVERT; j += blockDim.x) {
        sv[j] = g_vs[j];
        sidx[j] = g_vsidx[j];
    }
    for (int j = threadIdx.x; j < NVOXC; j += blockDim.x) scc[j] = g_ccdist[j];
    __syncthreads();

    float mnx, mny, mnz, dx, dy, dz;
    grid_params(mnx, mny, mnz, dx, dy, dz);
    float ivx = __fdiv_rn((float)GRES, dx);
    float ivy = __fdiv_rn((float)GRES, dy);
    float ivz = __fdiv_rn((float)GRES, dz);
    float* pout = out + 3 * NVERT;

    for (int i = blockIdx.x * blockDim.x + threadIdx.x; i < n;
         i += gridDim.x * blockDim.x) {
        float4 P = g_pts[i];                // coalesced
        float px = P.x, py = P.y, pz = P.z;
        int p = __float_as_int(P.w);
        float fx = (px - mnx) * ivx, fy = (py - mny) * ivy, fz = (pz - mnz) * ivz;
        int cx = min(max((int)floorf(fx), 0), GRES - 1);
        int cy = min(max((int)floorf(fy), 0), GRES - 1);
        int cz = min(max((int)floorf(fz), 0), GRES - 1);

        // ---- phase A: octant 2^3 box, bounds prefetched with MLP=8 ----
        float bestD = 3.402823466e38f;
        {
            int x0 = (fx - (float)cx > 0.5f) ? cx : cx - 1;
            int y0 = (fy - (float)cy > 0.5f) ? cy : cy - 1;
            int z0 = (fz - (float)cz > 0.5f) ? cz : cz - 1;
            x0 = max(x0, 0); int x1 = min(x0 + 1, GRES - 1); x0 = min(x0, x1);
            y0 = max(y0, 0); int y1 = min(y0 + 1, GRES - 1); y0 = min(y0, y1);
            z0 = max(z0, 0); int z1 = min(z0 + 1, GRES - 1); z0 = min(z0, z1);
            int r00 = (x0 * GRES + y0) * GRES;
            int r01 = (x0 * GRES + y1) * GRES;
            int r10 = (x1 * GRES + y0) * GRES;
            int r11 = (x1 * GRES + y1) * GRES;
            int s00 = v_off[r00 + z0], e00 = v_off[r00 + z1 + 1];
            int s01 = v_off[r01 + z0], e01 = v_off[r01 + z1 + 1];
            int s10 = v_off[r10 + z0], e10 = v_off[r10 + z1 + 1];
            int s11 = v_off[r11 + z0], e11 = v_off[r11 + z1 + 1];
            #pragma unroll 1
            for (int j = s00; j < e00; j++) {
                float4 V = sv[j];
                float ddx = px - 0.5f * V.x, ddy = py - 0.5f * V.y, ddz = pz - 0.5f * V.z;
                bestD = fminf(bestD, fmaf(ddz, ddz, fmaf(ddy, ddy, ddx * ddx)));
            }
            #pragma unroll 1
            for (int j = s01; j < e01; j++) {
                float4 V = sv[j];
                float ddx = px - 0.5f * V.x, ddy = py - 0.5f * V.y, ddz = pz - 0.5f * V.z;
                bestD = fminf(bestD, fmaf(ddz, ddz, fmaf(ddy, ddy, ddx * ddx)));
            }
            #pragma unroll 1
            for (int j = s10; j < e10; j++) {
                float4 V = sv[j];
                float ddx = px - 0.5f * V.x, ddy = py - 0.5f * V.y, ddz = pz - 0.5f * V.z;
                bestD = fminf(bestD, fmaf(ddz, ddz, fmaf(ddy, ddy, ddx * ddx)));
            }
            #pragma unroll 1
            for (int j = s11; j < e11; j++) {
                float4 V = sv[j];
                float ddx = px - 0.5f * V.x, ddy = py - 0.5f * V.y, ddz = pz - 0.5f * V.z;
                bestD = fminf(bestD, fmaf(ddz, ddz, fmaf(ddy, ddy, ddx * ddx)));
            }
        }

        float bd = 3.402823466e38f;
        int bi = 0x7FFFFFFF;

        if (bestD < 3.0e38f) {
            // ---- phase B (champion): sphere box, bounds MLP-batched 9 ----
            float R = sqrtf(bestD + 1e-4f) + 1e-4f;
            int x0 = min(max((int)floorf((px - R - mnx) * ivx), 0), GRES - 1);
            int x1 = min(max((int)floorf((px + R - mnx) * ivx), 0), GRES - 1);
            int y0 = min(max((int)floorf((py - R - mny) * ivy), 0), GRES - 1);
            int y1 = min(max((int)floorf((py + R - mny) * ivy), 0), GRES - 1);
            int z0 = min(max((int)floorf((pz - R - mnz) * ivz), 0), GRES - 1);
            int z1 = min(max((int)floorf((pz + R - mnz) * ivz), 0), GRES - 1);
            int nr = (x1 - x0 + 1) * (y1 - y0 + 1);
            const int NPF = 9;
            int sR[NPF], eR[NPF];
            int ix = x0, iy = y0;
            #pragma unroll
            for (int r = 0; r < NPF; r++) {
                if (r < nr) {
                    int rb = (ix * GRES + iy) * GRES;
                    sR[r] = v_off[rb + z0];
                    eR[r] = v_off[rb + z1 + 1];
                } else { sR[r] = 0; eR[r] = 0; }
                iy++; if (iy > y1) { iy = y0; ix++; }
            }
            #pragma unroll
            for (int r = 0; r < NPF; r++) {
                #pragma unroll 1
                for (int j = sR[r]; j < eR[r]; j++) EVAL_EXACT(j);
            }
            if (nr > NPF) {
                int rb = (ix * GRES + iy) * GRES;
                int sC = v_off[rb + z0], eC = v_off[rb + z1 + 1];
                for (int r = NPF; r < nr; r++) {
                    int nix = ix, niy = iy + 1;
                    if (niy > y1) { niy = y0; nix = ix + 1; }
                    int sN = 0, eN = 0;
                    if (r + 1 < nr) {
                        int nb = (nix * GRES + niy) * GRES;
                        sN = v_off[nb + z0];
                        eN = v_off[nb + z1 + 1];
                    }
                    #pragma unroll 1
                    for (int j = sC; j < eC; j++) EVAL_EXACT(j);
                    sC = sN; eC = eN; ix = nix; iy = niy;
                }
            }
        } else {
            // ---- empty octant: direct guaranteed box from ccdist ----
            int cc = ((cx >> 2) * GRESC + (cy >> 2)) * GRESC + (cz >> 2);
            float R = scc[cc] + 1e-3f;
            int x0 = min(max((int)floorf((px - R - mnx) * ivx), 0), GRES - 1);
            int x1 = min(max((int)floorf((px + R - mnx) * ivx), 0), GRES - 1);
            int y0 = min(max((int)floorf((py - R - mny) * ivy), 0), GRES - 1);
            int y1 = min(max((int)floorf((py + R - mny) * ivy), 0), GRES - 1);
            int z0 = min(max((int)floorf((pz - R - mnz) * ivz), 0), GRES - 1);
            int z1 = min(max((int)floorf((pz + R - mnz) * ivz), 0), GRES - 1);
            int nr = (x1 - x0 + 1) * (y1 - y0 + 1);
            int ix = x0, iy = y0;
            int done = 0;
            while (done < nr) {
                const int BPF = 16;
                int sR[BPF], eR[BPF];
                int cnt = min(nr - done, BPF);
                #pragma unroll
                for (int r = 0; r < BPF; r++) {
                    if (r < cnt) {
                        int rb = (ix * GRES + iy) * GRES;
                        sR[r] = v_off[rb + z0];
                        eR[r] = v_off[rb + z1 + 1];
                        iy++; if (iy > y1) { iy = y0; ix++; }
                    } else { sR[r] = 0; eR[r] = 0; }
                }
                #pragma unroll
                for (int r = 0; r < BPF; r++) {
                    #pragma unroll 1
                    for (int j = sR[r]; j < eR[r]; j++) EVAL_EXACT(j);
                }
                done += cnt;
            }
        }
        pout[p] = (float)bi;
    }
}

// ---------------- launch ----------------
extern "C" void kernel_launch(void* const* d_in, const int* in_sizes, int n_in,
                              void* d_out, int out_size) {
    const float* xyz = (const float*)d_in[0];
    int n = in_sizes[0] / 3;
    float* out = (float*)d_out;

    int* d_ghist; cudaGetSymbolAddress((void**)&d_ghist, g_hist);
    int* d_goff;  cudaGetSymbolAddress((void**)&d_goff,  g_off);
    int* d_gcur;  cudaGetSymbolAddress((void**)&d_gcur,  g_cur);
    int* d_vhist; cudaGetSymbolAddress((void**)&d_vhist, v_hist);
    int* d_voff;  cudaGetSymbolAddress((void**)&d_voff,  v_off);
    int* d_vcur;  cudaGetSymbolAddress((void**)&d_vcur,  v_cur);
    unsigned int* d_mm; cudaGetSymbolAddress((void**)&d_mm, g_mm);

    // init via memset nodes
    cudaMemsetAsync(d_ghist, 0, NVOX * sizeof(int));
    cudaMemsetAsync(d_vhist, 0, NVOX * sizeof(int));
    cudaMemsetAsync(d_mm, 0xFF, 3 * sizeof(unsigned int));
    cudaMemsetAsync(d_mm + 3, 0x00, 3 * sizeof(unsigned int));

    k_minmax<<<148, 256>>>(xyz, n);
    k_vidhist<<<1024, 256>>>(xyz, n);
    k_scan_a<<<SCANB, 512>>>(d_ghist);
    k_scan_b<<<1, 512>>>(d_goff, n);
    k_scan_c<<<SCANB, 512>>>(d_ghist, d_goff, d_gcur);
    k_scatter<<<1024, 256>>>(xyz, n);
    k_select<<<NVERT, 128>>>(out, n);
    k_ccdist<<<128, 1024>>>();
    k_scan_a<<<SCANB, 512>>>(d_vhist);
    k_scan_b<<<1, 512>>>(d_voff, NVERT);
    k_scan_c<<<SCANB, 512>>>(d_vhist, d_voff, d_vcur);
    k_vscatter<<<16, 512>>>();

    int smem = NVERT * (int)sizeof(float4) + NVERT * (int)sizeof(unsigned short)
             + NVOXC * (int)sizeof(float);
    cudaFuncSetAttribute(k_knn, cudaFuncAttributeMaxDynamicSharedMemorySize, smem);
    k_knn<<<148, 1024, smem>>>(out, n);
}